// round 15
// baseline (speedup 1.0000x reference)
#include <cuda_runtime.h>
#include <cuda_bf16.h>
#include <math.h>
#include <float.h>
#include <stdint.h>

#define NN   8192
#define DIN  384
#define DH   512
#define KTOP 6
#define DH2  256
#define K7NODES 16
#define NCAND 12
#define NRAW  24
#define BST  72
#define SCALE 0.044194173824159216f

// ---------------- scratch ---------------------------------------------------
__device__ float g_x[NN * DH];
__device__ float g_eh[NN * DH];
__device__ float g_et[NN * DH];
__device__ __nv_bfloat16 g_ehb[NN * DH];   // pre-scaled by SCALE
__device__ __nv_bfloat16 g_etb[NN * DH];
__device__ __nv_bfloat16 g_xsh[NN * DIN], g_xsl[NN * DIN];
__device__ __nv_bfloat16 g_xmh[NN * DH],  g_xml[NN * DH];
__device__ __nv_bfloat16 g_s1h[NN * DH],  g_s1l[NN * DH];
__device__ __nv_bfloat16 g_s2h[NN * DH],  g_s2l[NN * DH];
__device__ __nv_bfloat16 g_w1h[DIN * DH], g_w1l[DIN * DH];
__device__ __nv_bfloat16 g_whh[DH * DH],  g_whl[DH * DH];
__device__ __nv_bfloat16 g_wth[DH * DH],  g_wtl[DH * DH];
__device__ __nv_bfloat16 g_l1h[DH * DH],  g_l1l[DH * DH];
__device__ __nv_bfloat16 g_l2h[DH * DH],  g_l2l[DH * DH];
__device__ float g_emb[NN * DH];
__device__ float g_part1[32 * DH];
__device__ float g_part2[32 * DH];
__device__ int   g_candi[NN * NCAND];
__device__ float g_a[NN];
__device__ float g_Z[1];

__device__ __forceinline__ float lrelu(float v) { return v > 0.0f ? v : 0.01f * v; }

__device__ __forceinline__ float tanh_fast(float x) {
    float y;
    asm("tanh.approx.f32 %0, %1;" : "=f"(y) : "f"(x));
    return y;
}

__device__ __forceinline__ uint32_t saddr(const void* p) {
    return (uint32_t)__cvta_generic_to_shared(p);
}

__device__ __forceinline__ void ldsm4(unsigned r[4], uint32_t addr) {
    asm volatile("ldmatrix.sync.aligned.m8n8.x4.shared.b16 {%0,%1,%2,%3}, [%4];"
                 : "=r"(r[0]), "=r"(r[1]), "=r"(r[2]), "=r"(r[3]) : "r"(addr));
}

__device__ __forceinline__ void ldsm4t(unsigned r[4], uint32_t addr) {
    asm volatile("ldmatrix.sync.aligned.m8n8.x4.trans.shared.b16 {%0,%1,%2,%3}, [%4];"
                 : "=r"(r[0]), "=r"(r[1]), "=r"(r[2]), "=r"(r[3]) : "r"(addr));
}

__device__ __forceinline__ void mma_bf16(float* d, const unsigned a[4],
                                         unsigned b0, unsigned b1) {
    asm volatile("mma.sync.aligned.m16n8k16.row.col.f32.bf16.bf16.f32 "
                 "{%0,%1,%2,%3}, {%4,%5,%6,%7}, {%8,%9}, {%0,%1,%2,%3};"
                 : "+f"(d[0]), "+f"(d[1]), "+f"(d[2]), "+f"(d[3])
                 : "r"(a[0]), "r"(a[1]), "r"(a[2]), "r"(a[3]), "r"(b0), "r"(b1));
}

__device__ __forceinline__ void cpa16(uint32_t s, const void* g) {
    asm volatile("cp.async.cg.shared.global [%0], [%1], 16;" :: "r"(s), "l"(g));
}
__device__ __forceinline__ void cpa_commit() { asm volatile("cp.async.commit_group;"); }
#define CPWAIT0 asm volatile("cp.async.wait_group 0;")
#define CPWAIT1 asm volatile("cp.async.wait_group 1;")
#define CPWAIT2 asm volatile("cp.async.wait_group 2;")

__device__ __forceinline__ void split4(float4 v, __nv_bfloat16* hi, __nv_bfloat16* lo) {
    __nv_bfloat16 h0 = __float2bfloat16(v.x), h1 = __float2bfloat16(v.y);
    __nv_bfloat16 h2 = __float2bfloat16(v.z), h3 = __float2bfloat16(v.w);
    __nv_bfloat16 l0 = __float2bfloat16(v.x - __bfloat162float(h0));
    __nv_bfloat16 l1 = __float2bfloat16(v.y - __bfloat162float(h1));
    __nv_bfloat16 l2 = __float2bfloat16(v.z - __bfloat162float(h2));
    __nv_bfloat16 l3 = __float2bfloat16(v.w - __bfloat162float(h3));
    *(__nv_bfloat162*)(hi)     = __halves2bfloat162(h0, h1);
    *(__nv_bfloat162*)(hi + 2) = __halves2bfloat162(h2, h3);
    *(__nv_bfloat162*)(lo)     = __halves2bfloat162(l0, l1);
    *(__nv_bfloat162*)(lo + 2) = __halves2bfloat162(l2, l3);
}

// ---------------- K0: all fp32 -> bf16 hi/lo splits in one launch ----------
#define N0 (NN * DIN / 4)
#define N1 (DIN * DH / 4)
#define N2 (DH * DH / 4)
#define NSPLIT (N0 + N1 + 4 * N2)

__global__ void ksplit_all(const float* __restrict__ xs, const float* __restrict__ w1,
                           const float* __restrict__ wh, const float* __restrict__ wt,
                           const float* __restrict__ l1, const float* __restrict__ l2) {
    int i = blockIdx.x * 256 + threadIdx.x;
    if (i >= NSPLIT) return;
    const float* src; __nv_bfloat16 *hi, *lo; int j;
    if (i < N0)                    { j = i;                   src = xs; hi = g_xsh; lo = g_xsl; }
    else if (i < N0 + N1)          { j = i - N0;              src = w1; hi = g_w1h; lo = g_w1l; }
    else if (i < N0 + N1 + N2)     { j = i - N0 - N1;         src = wh; hi = g_whh; lo = g_whl; }
    else if (i < N0 + N1 + 2 * N2) { j = i - N0 - N1 - N2;    src = wt; hi = g_wth; lo = g_wtl; }
    else if (i < N0 + N1 + 3 * N2) { j = i - N0 - N1 - 2 * N2; src = l1; hi = g_l1h; lo = g_l1l; }
    else                           { j = i - N0 - N1 - 3 * N2; src = l2; hi = g_l2h; lo = g_l2l; }
    float4 v = ((const float4*)src)[j];
    split4(v, hi + (size_t)j * 4, lo + (size_t)j * 4);
}

// ---------------- tile loader (64x64 bf16 via cp.async) --------------------
__device__ __forceinline__ void load_tile64(uint32_t sbase, const __nv_bfloat16* g,
                                            int gstride) {
    int tid = threadIdx.x;
#pragma unroll
    for (int j = 0; j < 2; j++) {
        int u = tid + j * 256;
        int row = u >> 3, seg = (u & 7) * 8;
        cpa16(sbase + (row * BST + seg) * 2, g + (size_t)row * gstride + seg);
    }
}

// ---------------- K1: x = lrelu(x_s @ fc1_w + fc1_b) -----------------------
#define K1_SMEM (2 * 4 * 64 * BST * 2)
__global__ void __launch_bounds__(256) k1_tc(const float* __restrict__ bias) {
    extern __shared__ char sm1[];
    uint32_t base = saddr(sm1);
    const int TB = 64 * BST * 2;
    int bm = blockIdx.y * 64, bn = blockIdx.x * 64;
    int tid = threadIdx.x, warp = tid >> 5, lane = tid & 31;
    int wm = warp & 1, wn = warp >> 1;
    int lrow = lane & 15, lkoff = (lane >> 4) * 8;
    float acc[2][2][4] = {};
    const int NCH = DIN / 64;

    auto issue = [&](int c, int s) {
        load_tile64(base + (s * 4 + 0) * TB, g_xsh + (size_t)bm * DIN + c * 64, DIN);
        load_tile64(base + (s * 4 + 1) * TB, g_xsl + (size_t)bm * DIN + c * 64, DIN);
        load_tile64(base + (s * 4 + 2) * TB, g_w1h + (size_t)(c * 64) * DH + bn, DH);
        load_tile64(base + (s * 4 + 3) * TB, g_w1l + (size_t)(c * 64) * DH + bn, DH);
        cpa_commit();
    };
    issue(0, 0);
    for (int c = 0; c < NCH; c++) {
        if (c + 1 < NCH) { issue(c + 1, (c + 1) & 1); CPWAIT1; } else { CPWAIT0; }
        __syncthreads();
        int s = c & 1;
        uint32_t Ah = base + (s * 4 + 0) * TB, Al = base + (s * 4 + 1) * TB;
        uint32_t Bh = base + (s * 4 + 2) * TB, Bl = base + (s * 4 + 3) * TB;
#pragma unroll
        for (int ks = 0; ks < 4; ks++) {
            unsigned ah[2][4], al[2][4], ph[4], pl[4];
            int aoff = ((wm * 32 + lrow) * BST + ks * 16 + lkoff) * 2;
            ldsm4(ah[0], Ah + aoff);
            ldsm4(ah[1], Ah + aoff + 16 * BST * 2);
            ldsm4(al[0], Al + aoff);
            ldsm4(al[1], Al + aoff + 16 * BST * 2);
            int boff = ((ks * 16 + (lane & 7) + 8 * ((lane >> 3) & 1)) * BST +
                        wn * 16 + 8 * (lane >> 4)) * 2;
            ldsm4t(ph, Bh + boff);
            ldsm4t(pl, Bl + boff);
#pragma unroll
            for (int m = 0; m < 2; m++)
#pragma unroll
                for (int n = 0; n < 2; n++) {
                    mma_bf16(acc[m][n], ah[m], ph[n * 2], ph[n * 2 + 1]);
                    mma_bf16(acc[m][n], ah[m], pl[n * 2], pl[n * 2 + 1]);
                    mma_bf16(acc[m][n], al[m], ph[n * 2], ph[n * 2 + 1]);
                }
        }
        __syncthreads();
    }
#pragma unroll
    for (int m = 0; m < 2; m++)
#pragma unroll
        for (int n = 0; n < 2; n++) {
            int row = bm + wm * 32 + m * 16 + (lane >> 2);
            int col = bn + wn * 16 + n * 8 + (lane & 3) * 2;
            g_x[(size_t)row * DH + col]           = lrelu(acc[m][n][0] + bias[col]);
            g_x[(size_t)row * DH + col + 1]       = lrelu(acc[m][n][1] + bias[col + 1]);
            g_x[(size_t)(row + 8) * DH + col]     = lrelu(acc[m][n][2] + bias[col]);
            g_x[(size_t)(row + 8) * DH + col + 1] = lrelu(acc[m][n][3] + bias[col + 1]);
        }
}

// ---------------- K2: column partial sums ----------------------------------
__global__ void k2_colpart() {
    int c = blockIdx.x * 256 + threadIdx.x;
    int r0 = blockIdx.y * 256;
    float s = 0.0f;
    for (int i = 0; i < 256; i++) s += g_x[(r0 + i) * DH + c];
    g_part1[blockIdx.y * DH + c] = s;
}

// ---------------- K2bc: finish mean per-block, emit xm hi/lo ---------------
__global__ void __launch_bounds__(256) k2bc_xm() {
    __shared__ float mean_s[DH];
    int tid = threadIdx.x;
    for (int c = tid; c < DH; c += 256) {
        float s = 0.0f;
        for (int p = 0; p < 32; p++) s += g_part1[p * DH + c];
        mean_s[c] = s * (1.0f / NN);
    }
    __syncthreads();
    int r0 = blockIdx.x * 16;
    for (int u = tid; u < 16 * (DH / 4); u += 256) {
        int row = u >> 7, c4 = (u & 127) * 4;
        size_t off = (size_t)(r0 + row) * DH + c4;
        float4 v = *(const float4*)&g_x[off];
        float4 mu = *(const float4*)&mean_s[c4];
        v.x = (v.x + mu.x) * 0.5f; v.y = (v.y + mu.y) * 0.5f;
        v.z = (v.z + mu.z) * 0.5f; v.w = (v.w + mu.w) * 0.5f;
        split4(v, g_xmh + off, g_xml + off);
    }
}

// ---------------- K3: dual GEMM e_h / e_t ----------------------------------
#define K3_SMEM (2 * 6 * 64 * BST * 2)
__global__ void __launch_bounds__(256) k3_tc(const float* __restrict__ b1,
                                             const float* __restrict__ b2) {
    extern __shared__ char sm3[];
    uint32_t base = saddr(sm3);
    const int TB = 64 * BST * 2;
    int bm = blockIdx.y * 64, bn = blockIdx.x * 64;
    int tid = threadIdx.x, warp = tid >> 5, lane = tid & 31;
    int wm = warp & 1, wn = warp >> 1;
    int lrow = lane & 15, lkoff = (lane >> 4) * 8;
    float acc1[2][2][4] = {}, acc2[2][2][4] = {};
    const int NCH = DH / 64;

    auto issue = [&](int c, int s) {
        load_tile64(base + (s * 6 + 0) * TB, g_xmh + (size_t)bm * DH + c * 64, DH);
        load_tile64(base + (s * 6 + 1) * TB, g_xml + (size_t)bm * DH + c * 64, DH);
        load_tile64(base + (s * 6 + 2) * TB, g_whh + (size_t)(c * 64) * DH + bn, DH);
        load_tile64(base + (s * 6 + 3) * TB, g_whl + (size_t)(c * 64) * DH + bn, DH);
        load_tile64(base + (s * 6 + 4) * TB, g_wth + (size_t)(c * 64) * DH + bn, DH);
        load_tile64(base + (s * 6 + 5) * TB, g_wtl + (size_t)(c * 64) * DH + bn, DH);
        cpa_commit();
    };
    issue(0, 0);
    for (int c = 0; c < NCH; c++) {
        if (c + 1 < NCH) { issue(c + 1, (c + 1) & 1); CPWAIT1; } else { CPWAIT0; }
        __syncthreads();
        int s = c & 1;
        uint32_t Ah = base + (s * 6 + 0) * TB, Al = base + (s * 6 + 1) * TB;
        uint32_t B1h = base + (s * 6 + 2) * TB, B1l = base + (s * 6 + 3) * TB;
        uint32_t B2h = base + (s * 6 + 4) * TB, B2l = base + (s * 6 + 5) * TB;
#pragma unroll
        for (int ks = 0; ks < 4; ks++) {
            unsigned ah[2][4], al[2][4], p1h[4], p1l[4], p2h[4], p2l[4];
            int aoff = ((wm * 32 + lrow) * BST + ks * 16 + lkoff) * 2;
            ldsm4(ah[0], Ah + aoff);
            ldsm4(ah[1], Ah + aoff + 16 * BST * 2);
            ldsm4(al[0], Al + aoff);
            ldsm4(al[1], Al + aoff + 16 * BST * 2);
            int boff = ((ks * 16 + (lane & 7) + 8 * ((lane >> 3) & 1)) * BST +
                        wn * 16 + 8 * (lane >> 4)) * 2;
            ldsm4t(p1h, B1h + boff);
            ldsm4t(p1l, B1l + boff);
            ldsm4t(p2h, B2h + boff);
            ldsm4t(p2l, B2l + boff);
#pragma unroll
            for (int m = 0; m < 2; m++)
#pragma unroll
                for (int n = 0; n < 2; n++) {
                    mma_bf16(acc1[m][n], ah[m], p1h[n * 2], p1h[n * 2 + 1]);
                    mma_bf16(acc1[m][n], ah[m], p1l[n * 2], p1l[n * 2 + 1]);
                    mma_bf16(acc1[m][n], al[m], p1h[n * 2], p1h[n * 2 + 1]);
                    mma_bf16(acc2[m][n], ah[m], p2h[n * 2], p2h[n * 2 + 1]);
                    mma_bf16(acc2[m][n], ah[m], p2l[n * 2], p2l[n * 2 + 1]);
                    mma_bf16(acc2[m][n], al[m], p2h[n * 2], p2h[n * 2 + 1]);
                }
        }
        __syncthreads();
    }
#pragma unroll
    for (int m = 0; m < 2; m++)
#pragma unroll
        for (int n = 0; n < 2; n++) {
            int row = bm + wm * 32 + m * 16 + (lane >> 2);
            int col = bn + wn * 16 + n * 8 + (lane & 3) * 2;
            float v0 = acc1[m][n][0] + b1[col], v1 = acc1[m][n][1] + b1[col + 1];
            float v2 = acc1[m][n][2] + b1[col], v3 = acc1[m][n][3] + b1[col + 1];
            g_eh[(size_t)row * DH + col] = v0;       g_eh[(size_t)row * DH + col + 1] = v1;
            g_eh[(size_t)(row + 8) * DH + col] = v2; g_eh[(size_t)(row + 8) * DH + col + 1] = v3;
            g_ehb[(size_t)row * DH + col] = __float2bfloat16(v0 * SCALE);
            g_ehb[(size_t)row * DH + col + 1] = __float2bfloat16(v1 * SCALE);
            g_ehb[(size_t)(row + 8) * DH + col] = __float2bfloat16(v2 * SCALE);
            g_ehb[(size_t)(row + 8) * DH + col + 1] = __float2bfloat16(v3 * SCALE);
            float w0 = acc2[m][n][0] + b2[col], w1 = acc2[m][n][1] + b2[col + 1];
            float w2 = acc2[m][n][2] + b2[col], w3 = acc2[m][n][3] + b2[col + 1];
            g_et[(size_t)row * DH + col] = w0;       g_et[(size_t)row * DH + col + 1] = w1;
            g_et[(size_t)(row + 8) * DH + col] = w2; g_et[(size_t)(row + 8) * DH + col + 1] = w3;
            g_etb[(size_t)row * DH + col] = __float2bfloat16(w0);
            g_etb[(size_t)row * DH + col + 1] = __float2bfloat16(w1);
            g_etb[(size_t)(row + 8) * DH + col] = __float2bfloat16(w2);
            g_etb[(size_t)(row + 8) * DH + col + 1] = __float2bfloat16(w3);
        }
}

// ---------------- K4: score GEMM + register top-6 + block top-12 -----------
#define ASTRIDE 520
#define B4STRIDE 136
#define SMEM_A_BYTES (64 * ASTRIDE * 2)
#define B4_CHUNK_BYTES (128 * B4STRIDE * 2)
#define SMEM4_TOTAL (SMEM_A_BYTES + 4 * B4_CHUNK_BYTES)

__global__ void __launch_bounds__(512, 1) k4_tc() {
    extern __shared__ char sm4[];
    __nv_bfloat16* As = (__nv_bfloat16*)sm4;
    uint32_t bbase = saddr(sm4) + SMEM_A_BYTES;
    // candidate staging reuses B-buffer space after the mainloop
    float* cv = (float*)(sm4 + SMEM_A_BYTES);
    int*   ci = (int*)(sm4 + SMEM_A_BYTES + 64 * NRAW * 4);

    int tid = threadIdx.x;
    int warp = tid >> 5, lane = tid & 31;
    int wm = warp & 3, wn = warp >> 2;
    int bm = blockIdx.x * 64;
    int lrow = lane & 15, lkoff = (lane >> 4) * 8;
    int g = lane >> 2, tg = lane & 3;

    int ldrow = tid >> 2, ldseg = (tid & 3) * 32;
    uint32_t ldoff = (uint32_t)(ldrow * B4STRIDE + ldseg) * 2;

    auto issueB = [&](int q) {
        int st = q & 3;
        int tile = q >> 2, kc = q & 3;
        const __nv_bfloat16* src =
            g_etb + (size_t)(tile * 128 + ldrow) * DH + kc * 128 + ldseg;
        uint32_t dst = bbase + st * B4_CHUNK_BYTES + ldoff;
#pragma unroll
        for (int j = 0; j < 4; j++) cpa16(dst + j * 16, src + j * 8);
        cpa_commit();
    };

    issueB(0);
    issueB(1);
    issueB(2);

    for (int i = tid; i < 64 * 64; i += 512) {
        int row = i >> 6, c4 = i & 63;
        *(uint4*)(As + row * ASTRIDE + c4 * 8) =
            *(const uint4*)(g_ehb + (size_t)(bm + row) * DH + c4 * 8);
    }

    float tvA[KTOP], tvB[KTOP];
    int tiA[KTOP], tiB[KTOP];
#pragma unroll
    for (int k = 0; k < KTOP; k++) {
        tvA[k] = -FLT_MAX; tiA[k] = 0;
        tvB[k] = -FLT_MAX; tiB[k] = 0;
    }

    auto upd = [](float tv[KTOP], int ti[KTOP], float v, int c) {
        if (v > tv[KTOP - 1]) {
            tv[KTOP - 1] = v; ti[KTOP - 1] = c;
#pragma unroll
            for (int p = KTOP - 1; p > 0; p--) {
                if (tv[p] > tv[p - 1]) {
                    float tf = tv[p]; tv[p] = tv[p - 1]; tv[p - 1] = tf;
                    int tt = ti[p]; ti[p] = ti[p - 1]; ti[p - 1] = tt;
                }
            }
        }
    };

    float acc[4][4];
    for (int q = 0; q < 256; q++) {
        if (q <= 253) { CPWAIT2; } else if (q == 254) { CPWAIT1; } else { CPWAIT0; }
        __syncthreads();
        if (q + 3 < 256) issueB(q + 3);
        if ((q & 3) == 0) {
#pragma unroll
            for (int b = 0; b < 4; b++)
#pragma unroll
                for (int c = 0; c < 4; c++) acc[b][c] = 0.0f;
        }
        uint32_t Bs = bbase + (uint32_t)(q & 3) * B4_CHUNK_BYTES;
        int ch = q & 3;
#pragma unroll
        for (int ks = 0; ks < 8; ks++) {
            unsigned a0[4], b0[4], b1[4];
            int kA = ch * 128 + ks * 16 + lkoff;
            ldsm4(a0, saddr(&As[(wm * 16 + lrow) * ASTRIDE + kA]));
            uint32_t kB = (uint32_t)((wn * 32 + lrow) * B4STRIDE + ks * 16 + lkoff) * 2;
            ldsm4(b0, Bs + kB);
            ldsm4(b1, Bs + kB + 16 * B4STRIDE * 2);
            mma_bf16(acc[0], a0, b0[0], b0[2]);
            mma_bf16(acc[1], a0, b0[1], b0[3]);
            mma_bf16(acc[2], a0, b1[0], b1[2]);
            mma_bf16(acc[3], a0, b1[1], b1[3]);
        }
        if ((q & 3) == 3) {
            int tilec = (q >> 2) * 128 + wn * 32 + tg * 2;
#pragma unroll
            for (int nsub = 0; nsub < 4; nsub++) {
                int c0 = tilec + nsub * 8;
                upd(tvA, tiA, acc[nsub][0], c0);
                upd(tvA, tiA, acc[nsub][1], c0 + 1);
                upd(tvB, tiB, acc[nsub][2], c0);
                upd(tvB, tiB, acc[nsub][3], c0 + 1);
            }
        }
    }

    // merge 4 tg-lanes (same g) -> comb top-6 per row, staged into smem.
    auto merge4 = [&](float tv[KTOP], int ti[KTOP], int row) {
#pragma unroll
        for (int p = 0; p < KTOP; p++) {
            float bv = tv[0];
            int bi = ti[0];
            int bl = tg;
#pragma unroll
            for (int o = 1; o < 4; o <<= 1) {
                float ov = __shfl_xor_sync(0xffffffffu, bv, o);
                int oi = __shfl_xor_sync(0xffffffffu, bi, o);
                int ol = __shfl_xor_sync(0xffffffffu, bl, o);
                if (ov > bv || (ov == bv && oi < bi)) { bv = ov; bi = oi; bl = ol; }
            }
            if (bl == tg) {
#pragma unroll
                for (int z = 0; z < KTOP - 1; z++) { tv[z] = tv[z + 1]; ti[z] = ti[z + 1]; }
                tv[KTOP - 1] = -FLT_MAX; ti[KTOP - 1] = 0x7fffffff;
            }
            if (tg == 0) {
                cv[row * NRAW + wn * KTOP + p] = bv;
                ci[row * NRAW + wn * KTOP + p] = bi;
            }
        }
    };
    merge4(tvA, tiA, wm * 16 + g);
    merge4(tvB, tiB, wm * 16 + 8 + g);

    __syncthreads();
    // block-level select: top-12 by (bf16 value desc, index asc) of the 24.
    if (tid < 64) {
        float v[NRAW];
        int ix[NRAW];
#pragma unroll
        for (int c = 0; c < NRAW; c++) {
            v[c] = cv[tid * NRAW + c];
            ix[c] = ci[tid * NRAW + c];
        }
        unsigned used = 0;
#pragma unroll
        for (int p = 0; p < NCAND; p++) {
            float bv = -FLT_MAX; int bi = 0x7fffffff; int bc = 0;
#pragma unroll
            for (int c = 0; c < NRAW; c++) {
                if (!((used >> c) & 1u)) {
                    if (v[c] > bv || (v[c] == bv && ix[c] < bi)) {
                        bv = v[c]; bi = ix[c]; bc = c;
                    }
                }
            }
            used |= 1u << bc;
            g_candi[(size_t)(bm + tid) * NCAND + p] = bi;
        }
    }
}

// ---------------- K45: fused exact refinement + neighbor aggregation -------
__global__ void __launch_bounds__(256) k45_refine_neigh() {
    int node = blockIdx.x * 8 + (threadIdx.x >> 5);
    int lane = threadIdx.x & 31;

    float eh[16];
#pragma unroll
    for (int t = 0; t < 16; t++) eh[t] = g_eh[(size_t)node * DH + lane + t * 32];

    float vals[NCAND];
    int idxs[NCAND];
#pragma unroll
    for (int c = 0; c < NCAND; c++) {
        int idx = g_candi[(size_t)node * NCAND + c];
        idxs[c] = idx;
        const float* et = g_et + (size_t)idx * DH;
        float s = 0.0f;
#pragma unroll
        for (int t = 0; t < 16; t++) s += eh[t] * __ldg(&et[lane + t * 32]);
#pragma unroll
        for (int o = 16; o > 0; o >>= 1) s += __shfl_xor_sync(0xffffffffu, s, o);
        vals[c] = s * SCALE;
    }

    float w[KTOP];
    int idx6[KTOP];
    unsigned used = 0;
#pragma unroll
    for (int p = 0; p < KTOP; p++) {
        float bv = -FLT_MAX; int bi = 0x7fffffff; int bc = 0;
#pragma unroll
        for (int c = 0; c < NCAND; c++) {
            if (!((used >> c) & 1u)) {
                if (vals[c] > bv || (vals[c] == bv && idxs[c] < bi)) {
                    bv = vals[c]; bi = idxs[c]; bc = c;
                }
            }
        }
        used |= 1u << bc;
        w[p] = bv; idx6[p] = bi;
    }

    float p6[KTOP], ps = 0.0f;
#pragma unroll
    for (int k = 0; k < KTOP; k++) { p6[k] = __expf(w[k] - w[0]); ps += p6[k]; }
    float pinv = 1.0f / ps;
#pragma unroll
    for (int k = 0; k < KTOP; k++) p6[k] *= pinv;

    float nb[KTOP][16];
#pragma unroll
    for (int k = 0; k < KTOP; k++)
#pragma unroll
        for (int t = 0; t < 16; t++)
            nb[k][t] = __ldg(&g_et[(size_t)idx6[k] * DH + lane + t * 32]);

    float ka[KTOP];
#pragma unroll
    for (int k = 0; k < KTOP; k++) {
        float s = 0.0f;
#pragma unroll
        for (int t = 0; t < 16; t++) {
            float ehr  = p6[k] * nb[k][t] + (1.0f - p6[k]) * eh[t];
            float gate = tanh_fast(eh[t] + ehr);
            s += nb[k][t] * gate;
        }
#pragma unroll
        for (int o = 16; o > 0; o >>= 1) s += __shfl_xor_sync(0xffffffffu, s, o);
        ka[k] = s;
    }
    float km = ka[0];
#pragma unroll
    for (int k = 1; k < KTOP; k++) km = fmaxf(km, ka[k]);
    float kp[KTOP], ks = 0.0f;
#pragma unroll
    for (int k = 0; k < KTOP; k++) { kp[k] = __expf(ka[k] - km); ks += kp[k]; }
    float kinv = 1.0f / ks;
#pragma unroll
    for (int k = 0; k < KTOP; k++) kp[k] *= kinv;

#pragma unroll
    for (int t = 0; t < 16; t++) {
        float enh = 0.0f;
#pragma unroll
        for (int k = 0; k < KTOP; k++) enh += kp[k] * nb[k][t];
        size_t d = (size_t)node * DH + lane + t * 32;
        float s1v = eh[t] + enh;
        float s2v = eh[t] * enh;
        __nv_bfloat16 h1 = __float2bfloat16(s1v);
        __nv_bfloat16 h2 = __float2bfloat16(s2v);
        g_s1h[d] = h1; g_s1l[d] = __float2bfloat16(s1v - __bfloat162float(h1));
        g_s2h[d] = h2; g_s2l[d] = __float2bfloat16(s2v - __bfloat162float(h2));
    }
}

// ---------------- K6: emb (3-stage pipeline) --------------------------------
#define K6_SMEM (3 * 8 * 64 * BST * 2)
__global__ void __launch_bounds__(256) k6_tc(const float* __restrict__ b1,
                                             const float* __restrict__ b2) {
    extern __shared__ char sm6[];
    uint32_t base = saddr(sm6);
    const int TB = 64 * BST * 2;
    int bm = blockIdx.y * 64, bn = blockIdx.x * 64;
    int tid = threadIdx.x, warp = tid >> 5, lane = tid & 31;
    int wm = warp & 1, wn = warp >> 1;
    int lrow = lane & 15, lkoff = (lane >> 4) * 8;
    float acc1[2][2][4] = {}, acc2[2][2][4] = {};
    const int NCH = DH / 64;

    auto issue = [&](int c) {
        int s = c % 3;
        load_tile64(base + (s * 8 + 0) * TB, g_s1h + (size_t)bm * DH + c * 64, DH);
        load_tile64(base + (s * 8 + 1) * TB, g_s1l + (size_t)bm * DH + c * 64, DH);
        load_tile64(base + (s * 8 + 2) * TB, g_s2h + (size_t)bm * DH + c * 64, DH);
        load_tile64(base + (s * 8 + 3) * TB, g_s2l + (size_t)bm * DH + c * 64, DH);
        load_tile64(base + (s * 8 + 4) * TB, g_l1h + (size_t)(c * 64) * DH + bn, DH);
        load_tile64(base + (s * 8 + 5) * TB, g_l1l + (size_t)(c * 64) * DH + bn, DH);
        load_tile64(base + (s * 8 + 6) * TB, g_l2h + (size_t)(c * 64) * DH + bn, DH);
        load_tile64(base + (s * 8 + 7) * TB, g_l2l + (size_t)(c * 64) * DH + bn, DH);
        cpa_commit();
    };
    issue(0);
    issue(1);
    for (int c = 0; c < NCH; c++) {
        if (c < NCH - 1) { CPWAIT1; } else { CPWAIT0; }
        __syncthreads();
        if (c + 2 < NCH) issue(c + 2);
        int s = c % 3;
        uint32_t A1h = base + (s * 8 + 0) * TB, A1l = base + (s * 8 + 1) * TB;
        uint32_t A2h = base + (s * 8 + 2) * TB, A2l = base + (s * 8 + 3) * TB;
        uint32_t B1h = base + (s * 8 + 4) * TB, B1l = base + (s * 8 + 5) * TB;
        uint32_t B2h = base + (s * 8 + 6) * TB, B2l = base + (s * 8 + 7) * TB;
#pragma unroll
        for (int ks = 0; ks < 4; ks++) {
            unsigned a1h[2][4], a1l[2][4], a2h[2][4], a2l[2][4];
            int aoff = ((wm * 32 + lrow) * BST + ks * 16 + lkoff) * 2;
            ldsm4(a1h[0], A1h + aoff); ldsm4(a1h[1], A1h + aoff + 16 * BST * 2);
            ldsm4(a1l[0], A1l + aoff); ldsm4(a1l[1], A1l + aoff + 16 * BST * 2);
            ldsm4(a2h[0], A2h + aoff); ldsm4(a2h[1], A2h + aoff + 16 * BST * 2);
            ldsm4(a2l[0], A2l + aoff); ldsm4(a2l[1], A2l + aoff + 16 * BST * 2);
            int boff = ((ks * 16 + (lane & 7) + 8 * ((lane >> 3) & 1)) * BST +
                        wn * 16 + 8 * (lane >> 4)) * 2;
            unsigned p1h[4], p1l[4], p2h[4], p2l[4];
            ldsm4t(p1h, B1h + boff);
            ldsm4t(p1l, B1l + boff);
            ldsm4t(p2h, B2h + boff);
            ldsm4t(p2l, B2l + boff);
#pragma unroll
            for (int m = 0; m < 2; m++)
#pragma unroll
                for (int n = 0; n < 2; n++) {
                    mma_bf16(acc1[m][n], a1h[m], p1h[n * 2], p1h[n * 2 + 1]);
                    mma_bf16(acc1[m][n], a1h[m], p1l[n * 2], p1l[n * 2 + 1]);
                    mma_bf16(acc1[m][n], a1l[m], p1h[n * 2], p1h[n * 2 + 1]);
                    mma_bf16(acc2[m][n], a2h[m], p2h[n * 2], p2h[n * 2 + 1]);
                    mma_bf16(acc2[m][n], a2h[m], p2l[n * 2], p2l[n * 2 + 1]);
                    mma_bf16(acc2[m][n], a2l[m], p2h[n * 2], p2h[n * 2 + 1]);
                }
        }
        __syncthreads();
    }
#pragma unroll
    for (int m = 0; m < 2; m++)
#pragma unroll
        for (int n = 0; n < 2; n++) {
            int row = bm + wm * 32 + m * 16 + (lane >> 2);
            int col = bn + wn * 16 + n * 8 + (lane & 3) * 2;
            g_emb[(size_t)row * DH + col] =
                lrelu(acc1[m][n][0] + b1[col]) + lrelu(acc2[m][n][0] + b2[col]);
            g_emb[(size_t)row * DH + col + 1] =
                lrelu(acc1[m][n][1] + b1[col + 1]) + lrelu(acc2[m][n][1] + b2[col + 1]);
            g_emb[(size_t)(row + 8) * DH + col] =
                lrelu(acc1[m][n][2] + b1[col]) + lrelu(acc2[m][n][2] + b2[col]);
            g_emb[(size_t)(row + 8) * DH + col + 1] =
                lrelu(acc1[m][n][3] + b1[col + 1]) + lrelu(acc2[m][n][3] + b2[col + 1]);
        }
}

// ---------------- K7: node scores (single-sync epilogue) -------------------
__global__ void k7_readout(const float* __restrict__ att1_w, const float* __restrict__ att1_b,
                           const float* __restrict__ att2_w, const float* __restrict__ att2_b) {
    __shared__ float se[K7NODES][DH];
    __shared__ float warpred[K7NODES][8];
    int n0 = blockIdx.x * K7NODES;
    int tid = threadIdx.x;
    for (int i = tid; i < K7NODES * DH; i += 256)
        se[i >> 9][i & 511] = g_emb[(n0 + (i >> 9)) * DH + (i & 511)];
    __syncthreads();

    int j = tid;
    float acc[K7NODES];
#pragma unroll
    for (int m = 0; m < K7NODES; m++) acc[m] = 0.0f;

    for (int d = 0; d < DH; d += 4) {
        float w0 = att1_w[(d + 0) * DH2 + j];
        float w1 = att1_w[(d + 1) * DH2 + j];
        float w2 = att1_w[(d + 2) * DH2 + j];
        float w3 = att1_w[(d + 3) * DH2 + j];
#pragma unroll
        for (int m = 0; m < K7NODES; m++) {
            float4 e = *(const float4*)&se[m][d];
            acc[m] += e.x * w0 + e.y * w1 + e.z * w2 + e.w * w3;
        }
    }
    float b1 = att1_b[j], a2 = att2_w[j];
    int lane = tid & 31, wid = tid >> 5;
#pragma unroll
    for (int m = 0; m < K7NODES; m++) {
        float v = lrelu(acc[m] + b1) * a2;
#pragma unroll
        for (int o = 16; o > 0; o >>= 1) v += __shfl_xor_sync(0xffffffffu, v, o);
        if (lane == 0) warpred[m][wid] = v;
    }
    __syncthreads();
    if (tid < K7NODES) {
        float s = 0.0f;
#pragma unroll
        for (int q = 0; q < 8; q++) s += warpred[tid][q];
        g_a[n0 + tid] = s + att2_b[0];
    }
}

// ---------------- K8: softmax over nodes -----------------------------------
__global__ void k8_softmax() {
    __shared__ float red[1024];
    int tid = threadIdx.x;
    float lm = -FLT_MAX;
    for (int i = tid; i < NN; i += 1024) lm = fmaxf(lm, g_a[i]);
    red[tid] = lm;
    __syncthreads();
    for (int s = 512; s > 0; s >>= 1) {
        if (tid < s) red[tid] = fmaxf(red[tid], red[tid + s]);
        __syncthreads();
    }
    float amax = red[0];
    __syncthreads();
    float ls = 0.0f;
    for (int i = tid; i < NN; i += 1024) {
        float w = expf(g_a[i] - amax);
        g_a[i] = w;
        ls += w;
    }
    red[tid] = ls;
    __syncthreads();
    for (int s = 512; s > 0; s >>= 1) {
        if (tid < s) red[tid] += red[tid + s];
        __syncthreads();
    }
    if (tid == 0) g_Z[0] = red[0];
}

// ---------------- K9: weighted partial sums --------------------------------
__global__ void k9_wsum() {
    int d = blockIdx.x * 128 + threadIdx.x;
    int r0 = blockIdx.y * 256;
    float s = 0.0f;
    for (int i = 0; i < 256; i++) s += g_a[r0 + i] * g_emb[(r0 + i) * DH + d];
    g_part2[blockIdx.y * DH + d] = s;
}

// ---------------- K10: finalize --------------------------------------------
__global__ void k10_final(const float* __restrict__ ln_g, const float* __restrict__ ln_b,
                          const float* __restrict__ fc_w, const float* __restrict__ fc_b,
                          float* __restrict__ out) {
    __shared__ float red[DH];
    int tid = threadIdx.x;
    float raw = 0.0f;
    for (int p = 0; p < 32; p++) raw += g_part2[p * DH + tid];
    float h = raw / g_Z[0];

    red[tid] = h;
    __syncthreads();
    for (int s = 256; s > 0; s >>= 1) {
        if (tid < s) red[tid] += red[tid + s];
        __syncthreads();
    }
    float mu = red[0] * (1.0f / DH);
    __syncthreads();
    float dv = h - mu;
    red[tid] = dv * dv;
    __syncthreads();
    for (int s = 256; s > 0; s >>= 1) {
        if (tid < s) red[tid] += red[tid + s];
        __syncthreads();
    }
    float var = red[0] * (1.0f / DH);
    __syncthreads();
    float hn = dv * rsqrtf(var + 1e-5f) * ln_g[tid] + ln_b[tid];

    float p0 = hn * fc_w[tid * 2 + 0];
    float p1 = hn * fc_w[tid * 2 + 1];
    red[tid] = p0;
    __syncthreads();
    for (int s = 256; s > 0; s >>= 1) {
        if (tid < s) red[tid] += red[tid + s];
        __syncthreads();
    }
    float s0 = red[0];
    __syncthreads();
    red[tid] = p1;
    __syncthreads();
    for (int s = 256; s > 0; s >>= 1) {
        if (tid < s) red[tid] += red[tid + s];
        __syncthreads();
    }
    if (tid == 0) {
        out[0] = s0 + fc_b[0];
        out[1] = red[0] + fc_b[1];
    }
}

// ---------------- launch ---------------------------------------------------
extern "C" void kernel_launch(void* const* d_in, const int* in_sizes, int n_in,
                              void* d_out, int out_size) {
    (void)in_sizes; (void)n_in; (void)out_size;
    const float* x_s    = (const float*)d_in[0];
    const float* fc1_w  = (const float*)d_in[1];
    const float* fc1_b  = (const float*)d_in[2];
    const float* wh_w   = (const float*)d_in[3];
    const float* wh_b   = (const float*)d_in[4];
    const float* wt_w   = (const float*)d_in[5];
    const float* wt_b   = (const float*)d_in[6];
    const float* l1_w   = (const float*)d_in[7];
    const float* l1_b   = (const float*)d_in[8];
    const float* l2_w   = (const float*)d_in[9];
    const float* l2_b   = (const float*)d_in[10];
    const float* att1_w = (const float*)d_in[11];
    const float* att1_b = (const float*)d_in[12];
    const float* att2_w = (const float*)d_in[13];
    const float* att2_b = (const float*)d_in[14];
    const float* ln_g   = (const float*)d_in[15];
    const float* ln_b   = (const float*)d_in[16];
    const float* fc_w   = (const float*)d_in[17];
    const float* fc_b   = (const float*)d_in[18];
    float* out = (float*)d_out;

    static int smem_set = 0;
    if (!smem_set) {
        cudaFuncSetAttribute(k4_tc, cudaFuncAttributeMaxDynamicSharedMemorySize, SMEM4_TOTAL);
        cudaFuncSetAttribute(k1_tc, cudaFuncAttributeMaxDynamicSharedMemorySize, K1_SMEM);
        cudaFuncSetAttribute(k3_tc, cudaFuncAttributeMaxDynamicSharedMemorySize, K3_SMEM);
        cudaFuncSetAttribute(k6_tc, cudaFuncAttributeMaxDynamicSharedMemorySize, K6_SMEM);
        smem_set = 1;
    }

    dim3 gg(DH / 64, NN / 64);
    ksplit_all<<<(NSPLIT + 255) / 256, 256>>>(x_s, fc1_w, wh_w, wt_w, l1_w, l2_w);
    k1_tc<<<gg, 256, K1_SMEM>>>(fc1_b);
    k2_colpart<<<dim3(2, 32), 256>>>();
    k2bc_xm<<<NN / 16, 256>>>();
    k3_tc<<<gg, 256, K3_SMEM>>>(wh_b, wt_b);
    k4_tc<<<NN / 64, 512, SMEM4_TOTAL>>>();
    k45_refine_neigh<<<NN / 8, 256>>>();
    k6_tc<<<gg, 256, K6_SMEM>>>(l1_b, l2_b);
    k7_readout<<<NN / K7NODES, 256>>>(att1_w, att1_b, att2_w, att2_b);
    k8_softmax<<<1, 1024>>>();
    k9_wsum<<<dim3(4, 32), 128>>>();
    k10_final<<<1, DH>>>(ln_g, ln_b, fc_w, fc_b, out);
}

// round 16
// speedup vs baseline: 1.0259x; 1.0259x over previous
#include <cuda_runtime.h>
#include <cuda_bf16.h>
#include <math.h>
#include <float.h>
#include <stdint.h>

#define NN   8192
#define DIN  384
#define DH   512
#define KTOP 6
#define DH2  256
#define K7NODES 16
#define NCAND 24
#define BST  72
#define SCALE 0.044194173824159216f

// ---------------- scratch ---------------------------------------------------
__device__ float g_x[NN * DH];
__device__ float g_eh[NN * DH];
__device__ float g_et[NN * DH];
__device__ __nv_bfloat16 g_ehb[NN * DH];   // pre-scaled by SCALE
__device__ __nv_bfloat16 g_etb[NN * DH];
__device__ __nv_bfloat16 g_xsh[NN * DIN], g_xsl[NN * DIN];
__device__ __nv_bfloat16 g_xmh[NN * DH],  g_xml[NN * DH];
__device__ __nv_bfloat16 g_s1h[NN * DH],  g_s1l[NN * DH];
__device__ __nv_bfloat16 g_s2h[NN * DH],  g_s2l[NN * DH];
__device__ __nv_bfloat16 g_w1h[DIN * DH], g_w1l[DIN * DH];
__device__ __nv_bfloat16 g_whh[DH * DH],  g_whl[DH * DH];
__device__ __nv_bfloat16 g_wth[DH * DH],  g_wtl[DH * DH];
__device__ __nv_bfloat16 g_l1h[DH * DH],  g_l1l[DH * DH];
__device__ __nv_bfloat16 g_l2h[DH * DH],  g_l2l[DH * DH];
__device__ float g_emb[NN * DH];
__device__ float g_part1[128 * DH];
__device__ float g_mean[DH];
__device__ float g_part2[32 * DH];
__device__ int   g_candi[NN * NCAND];
__device__ float g_a[NN];
__device__ float g_Z[1];

__device__ __forceinline__ float lrelu(float v) { return v > 0.0f ? v : 0.01f * v; }

__device__ __forceinline__ float tanh_fast(float x) {
    float y;
    asm("tanh.approx.f32 %0, %1;" : "=f"(y) : "f"(x));
    return y;
}

__device__ __forceinline__ uint32_t saddr(const void* p) {
    return (uint32_t)__cvta_generic_to_shared(p);
}

__device__ __forceinline__ void ldsm4(unsigned r[4], uint32_t addr) {
    asm volatile("ldmatrix.sync.aligned.m8n8.x4.shared.b16 {%0,%1,%2,%3}, [%4];"
                 : "=r"(r[0]), "=r"(r[1]), "=r"(r[2]), "=r"(r[3]) : "r"(addr));
}

__device__ __forceinline__ void ldsm4t(unsigned r[4], uint32_t addr) {
    asm volatile("ldmatrix.sync.aligned.m8n8.x4.trans.shared.b16 {%0,%1,%2,%3}, [%4];"
                 : "=r"(r[0]), "=r"(r[1]), "=r"(r[2]), "=r"(r[3]) : "r"(addr));
}

__device__ __forceinline__ void mma_bf16(float* d, const unsigned a[4],
                                         unsigned b0, unsigned b1) {
    asm volatile("mma.sync.aligned.m16n8k16.row.col.f32.bf16.bf16.f32 "
                 "{%0,%1,%2,%3}, {%4,%5,%6,%7}, {%8,%9}, {%0,%1,%2,%3};"
                 : "+f"(d[0]), "+f"(d[1]), "+f"(d[2]), "+f"(d[3])
                 : "r"(a[0]), "r"(a[1]), "r"(a[2]), "r"(a[3]), "r"(b0), "r"(b1));
}

__device__ __forceinline__ void cpa16(uint32_t s, const void* g) {
    asm volatile("cp.async.cg.shared.global [%0], [%1], 16;" :: "r"(s), "l"(g));
}
__device__ __forceinline__ void cpa_commit() { asm volatile("cp.async.commit_group;"); }
#define CPWAIT0 asm volatile("cp.async.wait_group 0;")
#define CPWAIT1 asm volatile("cp.async.wait_group 1;")
#define CPWAIT2 asm volatile("cp.async.wait_group 2;")

__device__ __forceinline__ void split4(float4 v, __nv_bfloat16* hi, __nv_bfloat16* lo) {
    __nv_bfloat16 h0 = __float2bfloat16(v.x), h1 = __float2bfloat16(v.y);
    __nv_bfloat16 h2 = __float2bfloat16(v.z), h3 = __float2bfloat16(v.w);
    __nv_bfloat16 l0 = __float2bfloat16(v.x - __bfloat162float(h0));
    __nv_bfloat16 l1 = __float2bfloat16(v.y - __bfloat162float(h1));
    __nv_bfloat16 l2 = __float2bfloat16(v.z - __bfloat162float(h2));
    __nv_bfloat16 l3 = __float2bfloat16(v.w - __bfloat162float(h3));
    *(__nv_bfloat162*)(hi)     = __halves2bfloat162(h0, h1);
    *(__nv_bfloat162*)(hi + 2) = __halves2bfloat162(h2, h3);
    *(__nv_bfloat162*)(lo)     = __halves2bfloat162(l0, l1);
    *(__nv_bfloat162*)(lo + 2) = __halves2bfloat162(l2, l3);
}

// ---------------- K0: all fp32 -> bf16 hi/lo splits in one launch ----------
#define N0 (NN * DIN / 4)
#define N1 (DIN * DH / 4)
#define N2 (DH * DH / 4)
#define NSPLIT (N0 + N1 + 4 * N2)

__global__ void ksplit_all(const float* __restrict__ xs, const float* __restrict__ w1,
                           const float* __restrict__ wh, const float* __restrict__ wt,
                           const float* __restrict__ l1, const float* __restrict__ l2) {
    int i = blockIdx.x * 256 + threadIdx.x;
    if (i >= NSPLIT) return;
    const float* src; __nv_bfloat16 *hi, *lo; int j;
    if (i < N0)                    { j = i;                   src = xs; hi = g_xsh; lo = g_xsl; }
    else if (i < N0 + N1)          { j = i - N0;              src = w1; hi = g_w1h; lo = g_w1l; }
    else if (i < N0 + N1 + N2)     { j = i - N0 - N1;         src = wh; hi = g_whh; lo = g_whl; }
    else if (i < N0 + N1 + 2 * N2) { j = i - N0 - N1 - N2;    src = wt; hi = g_wth; lo = g_wtl; }
    else if (i < N0 + N1 + 3 * N2) { j = i - N0 - N1 - 2 * N2; src = l1; hi = g_l1h; lo = g_l1l; }
    else                           { j = i - N0 - N1 - 3 * N2; src = l2; hi = g_l2h; lo = g_l2l; }
    float4 v = ((const float4*)src)[j];
    split4(v, hi + (size_t)j * 4, lo + (size_t)j * 4);
}

// ---------------- tile loader (64x64 bf16 via cp.async) --------------------
__device__ __forceinline__ void load_tile64(uint32_t sbase, const __nv_bfloat16* g,
                                            int gstride) {
    int tid = threadIdx.x;
#pragma unroll
    for (int j = 0; j < 2; j++) {
        int u = tid + j * 256;
        int row = u >> 3, seg = (u & 7) * 8;
        cpa16(sbase + (row * BST + seg) * 2, g + (size_t)row * gstride + seg);
    }
}

// ---------------- K1: x = lrelu(x_s @ fc1_w + fc1_b) + column partials -----
#define K1_SMEM (2 * 4 * 64 * BST * 2)
#define SST 65
__global__ void __launch_bounds__(256) k1_tc(const float* __restrict__ bias) {
    extern __shared__ char sm1[];
    uint32_t base = saddr(sm1);
    const int TB = 64 * BST * 2;
    int bm = blockIdx.y * 64, bn = blockIdx.x * 64;
    int tid = threadIdx.x, warp = tid >> 5, lane = tid & 31;
    int wm = warp & 1, wn = warp >> 1;
    int lrow = lane & 15, lkoff = (lane >> 4) * 8;
    float acc[2][2][4] = {};
    const int NCH = DIN / 64;

    auto issue = [&](int c, int s) {
        load_tile64(base + (s * 4 + 0) * TB, g_xsh + (size_t)bm * DIN + c * 64, DIN);
        load_tile64(base + (s * 4 + 1) * TB, g_xsl + (size_t)bm * DIN + c * 64, DIN);
        load_tile64(base + (s * 4 + 2) * TB, g_w1h + (size_t)(c * 64) * DH + bn, DH);
        load_tile64(base + (s * 4 + 3) * TB, g_w1l + (size_t)(c * 64) * DH + bn, DH);
        cpa_commit();
    };
    issue(0, 0);
    for (int c = 0; c < NCH; c++) {
        if (c + 1 < NCH) { issue(c + 1, (c + 1) & 1); CPWAIT1; } else { CPWAIT0; }
        __syncthreads();
        int s = c & 1;
        uint32_t Ah = base + (s * 4 + 0) * TB, Al = base + (s * 4 + 1) * TB;
        uint32_t Bh = base + (s * 4 + 2) * TB, Bl = base + (s * 4 + 3) * TB;
#pragma unroll
        for (int ks = 0; ks < 4; ks++) {
            unsigned ah[2][4], al[2][4], ph[4], pl[4];
            int aoff = ((wm * 32 + lrow) * BST + ks * 16 + lkoff) * 2;
            ldsm4(ah[0], Ah + aoff);
            ldsm4(ah[1], Ah + aoff + 16 * BST * 2);
            ldsm4(al[0], Al + aoff);
            ldsm4(al[1], Al + aoff + 16 * BST * 2);
            int boff = ((ks * 16 + (lane & 7) + 8 * ((lane >> 3) & 1)) * BST +
                        wn * 16 + 8 * (lane >> 4)) * 2;
            ldsm4t(ph, Bh + boff);
            ldsm4t(pl, Bl + boff);
#pragma unroll
            for (int m = 0; m < 2; m++)
#pragma unroll
                for (int n = 0; n < 2; n++) {
                    mma_bf16(acc[m][n], ah[m], ph[n * 2], ph[n * 2 + 1]);
                    mma_bf16(acc[m][n], ah[m], pl[n * 2], pl[n * 2 + 1]);
                    mma_bf16(acc[m][n], al[m], ph[n * 2], ph[n * 2 + 1]);
                }
        }
        __syncthreads();
    }
    float* Stile = (float*)sm1;                         // 64 x SST, reuses buffers
    float* redp  = (float*)(sm1 + 64 * SST * 4);        // 4 x 64
#pragma unroll
    for (int m = 0; m < 2; m++)
#pragma unroll
        for (int n = 0; n < 2; n++) {
            int rloc = wm * 32 + m * 16 + (lane >> 2);
            int cloc = wn * 16 + n * 8 + (lane & 3) * 2;
            int row = bm + rloc, col = bn + cloc;
            float v0 = lrelu(acc[m][n][0] + bias[col]);
            float v1 = lrelu(acc[m][n][1] + bias[col + 1]);
            float v2 = lrelu(acc[m][n][2] + bias[col]);
            float v3 = lrelu(acc[m][n][3] + bias[col + 1]);
            g_x[(size_t)row * DH + col]           = v0;
            g_x[(size_t)row * DH + col + 1]       = v1;
            g_x[(size_t)(row + 8) * DH + col]     = v2;
            g_x[(size_t)(row + 8) * DH + col + 1] = v3;
            Stile[rloc * SST + cloc]           = v0;
            Stile[rloc * SST + cloc + 1]       = v1;
            Stile[(rloc + 8) * SST + cloc]     = v2;
            Stile[(rloc + 8) * SST + cloc + 1] = v3;
        }
    __syncthreads();
    {
        int qcol = tid & 63, qr = tid >> 6;             // 4 quarters of 16 rows
        float s = 0.0f;
        for (int r = qr * 16; r < qr * 16 + 16; r++) s += Stile[r * SST + qcol];
        redp[qr * 64 + qcol] = s;
    }
    __syncthreads();
    if (tid < 64) {
        float t = redp[tid] + redp[64 + tid] + redp[128 + tid] + redp[192 + tid];
        g_part1[(size_t)blockIdx.y * DH + bn + tid] = t;
    }
}

// ---------------- K2m: fold 128 row-block partials -> column mean ----------
__global__ void k2m() {
    int c = blockIdx.x * 256 + threadIdx.x;
    float s = 0.0f;
    for (int p = 0; p < 128; p++) s += g_part1[(size_t)p * DH + c];
    g_mean[c] = s * (1.0f / NN);
}

// ---------------- K2bc: emit xm hi/lo --------------------------------------
__global__ void __launch_bounds__(256) k2bc_xm() {
    __shared__ float mean_s[DH];
    int tid = threadIdx.x;
    for (int c = tid; c < DH; c += 256) mean_s[c] = g_mean[c];
    __syncthreads();
    int r0 = blockIdx.x * 16;
    for (int u = tid; u < 16 * (DH / 4); u += 256) {
        int row = u >> 7, c4 = (u & 127) * 4;
        size_t off = (size_t)(r0 + row) * DH + c4;
        float4 v = *(const float4*)&g_x[off];
        float4 mu = *(const float4*)&mean_s[c4];
        v.x = (v.x + mu.x) * 0.5f; v.y = (v.y + mu.y) * 0.5f;
        v.z = (v.z + mu.z) * 0.5f; v.w = (v.w + mu.w) * 0.5f;
        split4(v, g_xmh + off, g_xml + off);
    }
}

// ---------------- K3: dual GEMM e_h / e_t ----------------------------------
#define K3_SMEM (2 * 6 * 64 * BST * 2)
__global__ void __launch_bounds__(256) k3_tc(const float* __restrict__ b1,
                                             const float* __restrict__ b2) {
    extern __shared__ char sm3[];
    uint32_t base = saddr(sm3);
    const int TB = 64 * BST * 2;
    int bm = blockIdx.y * 64, bn = blockIdx.x * 64;
    int tid = threadIdx.x, warp = tid >> 5, lane = tid & 31;
    int wm = warp & 1, wn = warp >> 1;
    int lrow = lane & 15, lkoff = (lane >> 4) * 8;
    float acc1[2][2][4] = {}, acc2[2][2][4] = {};
    const int NCH = DH / 64;

    auto issue = [&](int c, int s) {
        load_tile64(base + (s * 6 + 0) * TB, g_xmh + (size_t)bm * DH + c * 64, DH);
        load_tile64(base + (s * 6 + 1) * TB, g_xml + (size_t)bm * DH + c * 64, DH);
        load_tile64(base + (s * 6 + 2) * TB, g_whh + (size_t)(c * 64) * DH + bn, DH);
        load_tile64(base + (s * 6 + 3) * TB, g_whl + (size_t)(c * 64) * DH + bn, DH);
        load_tile64(base + (s * 6 + 4) * TB, g_wth + (size_t)(c * 64) * DH + bn, DH);
        load_tile64(base + (s * 6 + 5) * TB, g_wtl + (size_t)(c * 64) * DH + bn, DH);
        cpa_commit();
    };
    issue(0, 0);
    for (int c = 0; c < NCH; c++) {
        if (c + 1 < NCH) { issue(c + 1, (c + 1) & 1); CPWAIT1; } else { CPWAIT0; }
        __syncthreads();
        int s = c & 1;
        uint32_t Ah = base + (s * 6 + 0) * TB, Al = base + (s * 6 + 1) * TB;
        uint32_t B1h = base + (s * 6 + 2) * TB, B1l = base + (s * 6 + 3) * TB;
        uint32_t B2h = base + (s * 6 + 4) * TB, B2l = base + (s * 6 + 5) * TB;
#pragma unroll
        for (int ks = 0; ks < 4; ks++) {
            unsigned ah[2][4], al[2][4], p1h[4], p1l[4], p2h[4], p2l[4];
            int aoff = ((wm * 32 + lrow) * BST + ks * 16 + lkoff) * 2;
            ldsm4(ah[0], Ah + aoff);
            ldsm4(ah[1], Ah + aoff + 16 * BST * 2);
            ldsm4(al[0], Al + aoff);
            ldsm4(al[1], Al + aoff + 16 * BST * 2);
            int boff = ((ks * 16 + (lane & 7) + 8 * ((lane >> 3) & 1)) * BST +
                        wn * 16 + 8 * (lane >> 4)) * 2;
            ldsm4t(p1h, B1h + boff);
            ldsm4t(p1l, B1l + boff);
            ldsm4t(p2h, B2h + boff);
            ldsm4t(p2l, B2l + boff);
#pragma unroll
            for (int m = 0; m < 2; m++)
#pragma unroll
                for (int n = 0; n < 2; n++) {
                    mma_bf16(acc1[m][n], ah[m], p1h[n * 2], p1h[n * 2 + 1]);
                    mma_bf16(acc1[m][n], ah[m], p1l[n * 2], p1l[n * 2 + 1]);
                    mma_bf16(acc1[m][n], al[m], p1h[n * 2], p1h[n * 2 + 1]);
                    mma_bf16(acc2[m][n], ah[m], p2h[n * 2], p2h[n * 2 + 1]);
                    mma_bf16(acc2[m][n], ah[m], p2l[n * 2], p2l[n * 2 + 1]);
                    mma_bf16(acc2[m][n], al[m], p2h[n * 2], p2h[n * 2 + 1]);
                }
        }
        __syncthreads();
    }
#pragma unroll
    for (int m = 0; m < 2; m++)
#pragma unroll
        for (int n = 0; n < 2; n++) {
            int row = bm + wm * 32 + m * 16 + (lane >> 2);
            int col = bn + wn * 16 + n * 8 + (lane & 3) * 2;
            float v0 = acc1[m][n][0] + b1[col], v1 = acc1[m][n][1] + b1[col + 1];
            float v2 = acc1[m][n][2] + b1[col], v3 = acc1[m][n][3] + b1[col + 1];
            g_eh[(size_t)row * DH + col] = v0;       g_eh[(size_t)row * DH + col + 1] = v1;
            g_eh[(size_t)(row + 8) * DH + col] = v2; g_eh[(size_t)(row + 8) * DH + col + 1] = v3;
            g_ehb[(size_t)row * DH + col] = __float2bfloat16(v0 * SCALE);
            g_ehb[(size_t)row * DH + col + 1] = __float2bfloat16(v1 * SCALE);
            g_ehb[(size_t)(row + 8) * DH + col] = __float2bfloat16(v2 * SCALE);
            g_ehb[(size_t)(row + 8) * DH + col + 1] = __float2bfloat16(v3 * SCALE);
            float w0 = acc2[m][n][0] + b2[col], w1 = acc2[m][n][1] + b2[col + 1];
            float w2 = acc2[m][n][2] + b2[col], w3 = acc2[m][n][3] + b2[col + 1];
            g_et[(size_t)row * DH + col] = w0;       g_et[(size_t)row * DH + col + 1] = w1;
            g_et[(size_t)(row + 8) * DH + col] = w2; g_et[(size_t)(row + 8) * DH + col + 1] = w3;
            g_etb[(size_t)row * DH + col] = __float2bfloat16(w0);
            g_etb[(size_t)row * DH + col + 1] = __float2bfloat16(w1);
            g_etb[(size_t)(row + 8) * DH + col] = __float2bfloat16(w2);
            g_etb[(size_t)(row + 8) * DH + col + 1] = __float2bfloat16(w3);
        }
}

// ---------------- K4: score GEMM + register top-6 (4-stage pipeline) -------
#define ASTRIDE 520
#define B4STRIDE 136
#define SMEM_A_BYTES (64 * ASTRIDE * 2)
#define B4_CHUNK_BYTES (128 * B4STRIDE * 2)
#define SMEM4_TOTAL (SMEM_A_BYTES + 4 * B4_CHUNK_BYTES)

__global__ void __launch_bounds__(512, 1) k4_tc() {
    extern __shared__ char sm4[];
    __nv_bfloat16* As = (__nv_bfloat16*)sm4;
    uint32_t bbase = saddr(sm4) + SMEM_A_BYTES;

    int tid = threadIdx.x;
    int warp = tid >> 5, lane = tid & 31;
    int wm = warp & 3, wn = warp >> 2;
    int bm = blockIdx.x * 64;
    int lrow = lane & 15, lkoff = (lane >> 4) * 8;
    int g = lane >> 2, tg = lane & 3;

    int ldrow = tid >> 2, ldseg = (tid & 3) * 32;
    uint32_t ldoff = (uint32_t)(ldrow * B4STRIDE + ldseg) * 2;

    auto issueB = [&](int q) {
        int st = q & 3;
        int tile = q >> 2, kc = q & 3;
        const __nv_bfloat16* src =
            g_etb + (size_t)(tile * 128 + ldrow) * DH + kc * 128 + ldseg;
        uint32_t dst = bbase + st * B4_CHUNK_BYTES + ldoff;
#pragma unroll
        for (int j = 0; j < 4; j++) cpa16(dst + j * 16, src + j * 8);
        cpa_commit();
    };

    issueB(0);
    issueB(1);
    issueB(2);

    for (int i = tid; i < 64 * 64; i += 512) {
        int row = i >> 6, c4 = i & 63;
        *(uint4*)(As + row * ASTRIDE + c4 * 8) =
            *(const uint4*)(g_ehb + (size_t)(bm + row) * DH + c4 * 8);
    }

    float tvA[KTOP], tvB[KTOP];
    int tiA[KTOP], tiB[KTOP];
#pragma unroll
    for (int k = 0; k < KTOP; k++) {
        tvA[k] = -FLT_MAX; tiA[k] = 0;
        tvB[k] = -FLT_MAX; tiB[k] = 0;
    }

    auto upd = [](float tv[KTOP], int ti[KTOP], float v, int c) {
        if (v > tv[KTOP - 1]) {
            tv[KTOP - 1] = v; ti[KTOP - 1] = c;
#pragma unroll
            for (int p = KTOP - 1; p > 0; p--) {
                if (tv[p] > tv[p - 1]) {
                    float tf = tv[p]; tv[p] = tv[p - 1]; tv[p - 1] = tf;
                    int tt = ti[p]; ti[p] = ti[p - 1]; ti[p - 1] = tt;
                }
            }
        }
    };

    float acc[4][4];
    for (int q = 0; q < 256; q++) {
        if (q <= 253) { CPWAIT2; } else if (q == 254) { CPWAIT1; } else { CPWAIT0; }
        __syncthreads();
        if (q + 3 < 256) issueB(q + 3);
        if ((q & 3) == 0) {
#pragma unroll
            for (int b = 0; b < 4; b++)
#pragma unroll
                for (int c = 0; c < 4; c++) acc[b][c] = 0.0f;
        }
        uint32_t Bs = bbase + (uint32_t)(q & 3) * B4_CHUNK_BYTES;
        int ch = q & 3;
#pragma unroll
        for (int ks = 0; ks < 8; ks++) {
            unsigned a0[4], b0[4], b1[4];
            int kA = ch * 128 + ks * 16 + lkoff;
            ldsm4(a0, saddr(&As[(wm * 16 + lrow) * ASTRIDE + kA]));
            uint32_t kB = (uint32_t)((wn * 32 + lrow) * B4STRIDE + ks * 16 + lkoff) * 2;
            ldsm4(b0, Bs + kB);
            ldsm4(b1, Bs + kB + 16 * B4STRIDE * 2);
            mma_bf16(acc[0], a0, b0[0], b0[2]);
            mma_bf16(acc[1], a0, b0[1], b0[3]);
            mma_bf16(acc[2], a0, b1[0], b1[2]);
            mma_bf16(acc[3], a0, b1[1], b1[3]);
        }
        if ((q & 3) == 3) {
            int tilec = (q >> 2) * 128 + wn * 32 + tg * 2;
#pragma unroll
            for (int nsub = 0; nsub < 4; nsub++) {
                int c0 = tilec + nsub * 8;
                upd(tvA, tiA, acc[nsub][0], c0);
                upd(tvA, tiA, acc[nsub][1], c0 + 1);
                upd(tvB, tiB, acc[nsub][2], c0);
                upd(tvB, tiB, acc[nsub][3], c0 + 1);
            }
        }
    }

    // merge 4 tg-lanes (same g) -> comb top-6 per row; STATIC indices only.
    auto merge4 = [&](float tv[KTOP], int ti[KTOP], int row) {
#pragma unroll
        for (int p = 0; p < KTOP; p++) {
            float bv = tv[0];
            int bi = ti[0];
            int bl = tg;
#pragma unroll
            for (int o = 1; o < 4; o <<= 1) {
                float ov = __shfl_xor_sync(0xffffffffu, bv, o);
                int oi = __shfl_xor_sync(0xffffffffu, bi, o);
                int ol = __shfl_xor_sync(0xffffffffu, bl, o);
                if (ov > bv || (ov == bv && oi < bi)) { bv = ov; bi = oi; bl = ol; }
            }
            if (bl == tg) {
#pragma unroll
                for (int z = 0; z < KTOP - 1; z++) { tv[z] = tv[z + 1]; ti[z] = ti[z + 1]; }
                tv[KTOP - 1] = -FLT_MAX; ti[KTOP - 1] = 0x7fffffff;
            }
            if (tg == 0)
                g_candi[(size_t)(bm + row) * NCAND + wn * KTOP + p] = bi;
        }
    };
    merge4(tvA, tiA, wm * 16 + g);
    merge4(tvB, tiB, wm * 16 + 8 + g);
}

// ---------------- K45: fused exact refinement + neighbor aggregation -------
__global__ void __launch_bounds__(256) k45_refine_neigh() {
    int node = blockIdx.x * 8 + (threadIdx.x >> 5);
    int lane = threadIdx.x & 31;

    float eh[16];
#pragma unroll
    for (int t = 0; t < 16; t++) eh[t] = g_eh[(size_t)node * DH + lane + t * 32];

    float vals[NCAND];
    int idxs[NCAND];
#pragma unroll
    for (int c = 0; c < NCAND; c++) {
        int idx = g_candi[(size_t)node * NCAND + c];
        idxs[c] = idx;
        const float* et = g_et + (size_t)idx * DH;
        float s = 0.0f;
#pragma unroll
        for (int t = 0; t < 16; t++) s += eh[t] * __ldg(&et[lane + t * 32]);
#pragma unroll
        for (int o = 16; o > 0; o >>= 1) s += __shfl_xor_sync(0xffffffffu, s, o);
        vals[c] = s * SCALE;
    }

    float w[KTOP];
    int idx6[KTOP];
    unsigned used = 0;
#pragma unroll
    for (int p = 0; p < KTOP; p++) {
        float bv = -FLT_MAX; int bi = 0x7fffffff; int bc = 0;
#pragma unroll
        for (int c = 0; c < NCAND; c++) {
            if (!((used >> c) & 1u)) {
                if (vals[c] > bv || (vals[c] == bv && idxs[c] < bi)) {
                    bv = vals[c]; bi = idxs[c]; bc = c;
                }
            }
        }
        used |= 1u << bc;
        w[p] = bv; idx6[p] = bi;
    }

    float p6[KTOP], ps = 0.0f;
#pragma unroll
    for (int k = 0; k < KTOP; k++) { p6[k] = __expf(w[k] - w[0]); ps += p6[k]; }
    float pinv = 1.0f / ps;
#pragma unroll
    for (int k = 0; k < KTOP; k++) p6[k] *= pinv;

    float nb[KTOP][16];
#pragma unroll
    for (int k = 0; k < KTOP; k++)
#pragma unroll
        for (int t = 0; t < 16; t++)
            nb[k][t] = __ldg(&g_et[(size_t)idx6[k] * DH + lane + t * 32]);

    float ka[KTOP];
#pragma unroll
    for (int k = 0; k < KTOP; k++) {
        float s = 0.0f;
#pragma unroll
        for (int t = 0; t < 16; t++) {
            float ehr  = p6[k] * nb[k][t] + (1.0f - p6[k]) * eh[t];
            float gate = tanh_fast(eh[t] + ehr);
            s += nb[k][t] * gate;
        }
#pragma unroll
        for (int o = 16; o > 0; o >>= 1) s += __shfl_xor_sync(0xffffffffu, s, o);
        ka[k] = s;
    }
    float km = ka[0];
#pragma unroll
    for (int k = 1; k < KTOP; k++) km = fmaxf(km, ka[k]);
    float kp[KTOP], ks = 0.0f;
#pragma unroll
    for (int k = 0; k < KTOP; k++) { kp[k] = __expf(ka[k] - km); ks += kp[k]; }
    float kinv = 1.0f / ks;
#pragma unroll
    for (int k = 0; k < KTOP; k++) kp[k] *= kinv;

#pragma unroll
    for (int t = 0; t < 16; t++) {
        float enh = 0.0f;
#pragma unroll
        for (int k = 0; k < KTOP; k++) enh += kp[k] * nb[k][t];
        size_t d = (size_t)node * DH + lane + t * 32;
        float s1v = eh[t] + enh;
        float s2v = eh[t] * enh;
        __nv_bfloat16 h1 = __float2bfloat16(s1v);
        __nv_bfloat16 h2 = __float2bfloat16(s2v);
        g_s1h[d] = h1; g_s1l[d] = __float2bfloat16(s1v - __bfloat162float(h1));
        g_s2h[d] = h2; g_s2l[d] = __float2bfloat16(s2v - __bfloat162float(h2));
    }
}

// ---------------- K6: emb (3-stage pipeline) --------------------------------
#define K6_SMEM (3 * 8 * 64 * BST * 2)
__global__ void __launch_bounds__(256) k6_tc(const float* __restrict__ b1,
                                             const float* __restrict__ b2) {
    extern __shared__ char sm6[];
    uint32_t base = saddr(sm6);
    const int TB = 64 * BST * 2;
    int bm = blockIdx.y * 64, bn = blockIdx.x * 64;
    int tid = threadIdx.x, warp = tid >> 5, lane = tid & 31;
    int wm = warp & 1, wn = warp >> 1;
    int lrow = lane & 15, lkoff = (lane >> 4) * 8;
    float acc1[2][2][4] = {}, acc2[2][2][4] = {};
    const int NCH = DH / 64;

    auto issue = [&](int c) {
        int s = c % 3;
        load_tile64(base + (s * 8 + 0) * TB, g_s1h + (size_t)bm * DH + c * 64, DH);
        load_tile64(base + (s * 8 + 1) * TB, g_s1l + (size_t)bm * DH + c * 64, DH);
        load_tile64(base + (s * 8 + 2) * TB, g_s2h + (size_t)bm * DH + c * 64, DH);
        load_tile64(base + (s * 8 + 3) * TB, g_s2l + (size_t)bm * DH + c * 64, DH);
        load_tile64(base + (s * 8 + 4) * TB, g_l1h + (size_t)(c * 64) * DH + bn, DH);
        load_tile64(base + (s * 8 + 5) * TB, g_l1l + (size_t)(c * 64) * DH + bn, DH);
        load_tile64(base + (s * 8 + 6) * TB, g_l2h + (size_t)(c * 64) * DH + bn, DH);
        load_tile64(base + (s * 8 + 7) * TB, g_l2l + (size_t)(c * 64) * DH + bn, DH);
        cpa_commit();
    };
    issue(0);
    issue(1);
    for (int c = 0; c < NCH; c++) {
        if (c < NCH - 1) { CPWAIT1; } else { CPWAIT0; }
        __syncthreads();
        if (c + 2 < NCH) issue(c + 2);
        int s = c % 3;
        uint32_t A1h = base + (s * 8 + 0) * TB, A1l = base + (s * 8 + 1) * TB;
        uint32_t A2h = base + (s * 8 + 2) * TB, A2l = base + (s * 8 + 3) * TB;
        uint32_t B1h = base + (s * 8 + 4) * TB, B1l = base + (s * 8 + 5) * TB;
        uint32_t B2h = base + (s * 8 + 6) * TB, B2l = base + (s * 8 + 7) * TB;
#pragma unroll
        for (int ks = 0; ks < 4; ks++) {
            unsigned a1h[2][4], a1l[2][4], a2h[2][4], a2l[2][4];
            int aoff = ((wm * 32 + lrow) * BST + ks * 16 + lkoff) * 2;
            ldsm4(a1h[0], A1h + aoff); ldsm4(a1h[1], A1h + aoff + 16 * BST * 2);
            ldsm4(a1l[0], A1l + aoff); ldsm4(a1l[1], A1l + aoff + 16 * BST * 2);
            ldsm4(a2h[0], A2h + aoff); ldsm4(a2h[1], A2h + aoff + 16 * BST * 2);
            ldsm4(a2l[0], A2l + aoff); ldsm4(a2l[1], A2l + aoff + 16 * BST * 2);
            int boff = ((ks * 16 + (lane & 7) + 8 * ((lane >> 3) & 1)) * BST +
                        wn * 16 + 8 * (lane >> 4)) * 2;
            unsigned p1h[4], p1l[4], p2h[4], p2l[4];
            ldsm4t(p1h, B1h + boff);
            ldsm4t(p1l, B1l + boff);
            ldsm4t(p2h, B2h + boff);
            ldsm4t(p2l, B2l + boff);
#pragma unroll
            for (int m = 0; m < 2; m++)
#pragma unroll
                for (int n = 0; n < 2; n++) {
                    mma_bf16(acc1[m][n], a1h[m], p1h[n * 2], p1h[n * 2 + 1]);
                    mma_bf16(acc1[m][n], a1h[m], p1l[n * 2], p1l[n * 2 + 1]);
                    mma_bf16(acc1[m][n], a1l[m], p1h[n * 2], p1h[n * 2 + 1]);
                    mma_bf16(acc2[m][n], a2h[m], p2h[n * 2], p2h[n * 2 + 1]);
                    mma_bf16(acc2[m][n], a2h[m], p2l[n * 2], p2l[n * 2 + 1]);
                    mma_bf16(acc2[m][n], a2l[m], p2h[n * 2], p2h[n * 2 + 1]);
                }
        }
        __syncthreads();
    }
#pragma unroll
    for (int m = 0; m < 2; m++)
#pragma unroll
        for (int n = 0; n < 2; n++) {
            int row = bm + wm * 32 + m * 16 + (lane >> 2);
            int col = bn + wn * 16 + n * 8 + (lane & 3) * 2;
            g_emb[(size_t)row * DH + col] =
                lrelu(acc1[m][n][0] + b1[col]) + lrelu(acc2[m][n][0] + b2[col]);
            g_emb[(size_t)row * DH + col + 1] =
                lrelu(acc1[m][n][1] + b1[col + 1]) + lrelu(acc2[m][n][1] + b2[col + 1]);
            g_emb[(size_t)(row + 8) * DH + col] =
                lrelu(acc1[m][n][2] + b1[col]) + lrelu(acc2[m][n][2] + b2[col]);
            g_emb[(size_t)(row + 8) * DH + col + 1] =
                lrelu(acc1[m][n][3] + b1[col + 1]) + lrelu(acc2[m][n][3] + b2[col + 1]);
        }
}

// ---------------- K7: node scores (single-sync epilogue) -------------------
__global__ void k7_readout(const float* __restrict__ att1_w, const float* __restrict__ att1_b,
                           const float* __restrict__ att2_w, const float* __restrict__ att2_b) {
    __shared__ float se[K7NODES][DH];
    __shared__ float warpred[K7NODES][8];
    int n0 = blockIdx.x * K7NODES;
    int tid = threadIdx.x;
    for (int i = tid; i < K7NODES * DH; i += 256)
        se[i >> 9][i & 511] = g_emb[(n0 + (i >> 9)) * DH + (i & 511)];
    __syncthreads();

    int j = tid;
    float acc[K7NODES];
#pragma unroll
    for (int m = 0; m < K7NODES; m++) acc[m] = 0.0f;

    for (int d = 0; d < DH; d += 4) {
        float w0 = att1_w[(d + 0) * DH2 + j];
        float w1 = att1_w[(d + 1) * DH2 + j];
        float w2 = att1_w[(d + 2) * DH2 + j];
        float w3 = att1_w[(d + 3) * DH2 + j];
#pragma unroll
        for (int m = 0; m < K7NODES; m++) {
            float4 e = *(const float4*)&se[m][d];
            acc[m] += e.x * w0 + e.y * w1 + e.z * w2 + e.w * w3;
        }
    }
    float b1 = att1_b[j], a2 = att2_w[j];
    int lane = tid & 31, wid = tid >> 5;
#pragma unroll
    for (int m = 0; m < K7NODES; m++) {
        float v = lrelu(acc[m] + b1) * a2;
#pragma unroll
        for (int o = 16; o > 0; o >>= 1) v += __shfl_xor_sync(0xffffffffu, v, o);
        if (lane == 0) warpred[m][wid] = v;
    }
    __syncthreads();
    if (tid < K7NODES) {
        float s = 0.0f;
#pragma unroll
        for (int q = 0; q < 8; q++) s += warpred[tid][q];
        g_a[n0 + tid] = s + att2_b[0];
    }
}

// ---------------- K8: softmax over nodes -----------------------------------
__global__ void k8_softmax() {
    __shared__ float red[1024];
    int tid = threadIdx.x;
    float lm = -FLT_MAX;
    for (int i = tid; i < NN; i += 1024) lm = fmaxf(lm, g_a[i]);
    red[tid] = lm;
    __syncthreads();
    for (int s = 512; s > 0; s >>= 1) {
        if (tid < s) red[tid] = fmaxf(red[tid], red[tid + s]);
        __syncthreads();
    }
    float amax = red[0];
    __syncthreads();
    float ls = 0.0f;
    for (int i = tid; i < NN; i += 1024) {
        float w = expf(g_a[i] - amax);
        g_a[i] = w;
        ls += w;
    }
    red[tid] = ls;
    __syncthreads();
    for (int s = 512; s > 0; s >>= 1) {
        if (tid < s) red[tid] += red[tid + s];
        __syncthreads();
    }
    if (tid == 0) g_Z[0] = red[0];
}

// ---------------- K9: weighted partial sums --------------------------------
__global__ void k9_wsum() {
    int d = blockIdx.x * 128 + threadIdx.x;
    int r0 = blockIdx.y * 256;
    float s = 0.0f;
    for (int i = 0; i < 256; i++) s += g_a[r0 + i] * g_emb[(r0 + i) * DH + d];
    g_part2[blockIdx.y * DH + d] = s;
}

// ---------------- K10: finalize --------------------------------------------
__global__ void k10_final(const float* __restrict__ ln_g, const float* __restrict__ ln_b,
                          const float* __restrict__ fc_w, const float* __restrict__ fc_b,
                          float* __restrict__ out) {
    __shared__ float red[DH];
    int tid = threadIdx.x;
    float raw = 0.0f;
    for (int p = 0; p < 32; p++) raw += g_part2[p * DH + tid];
    float h = raw / g_Z[0];

    red[tid] = h;
    __syncthreads();
    for (int s = 256; s > 0; s >>= 1) {
        if (tid < s) red[tid] += red[tid + s];
        __syncthreads();
    }
    float mu = red[0] * (1.0f / DH);
    __syncthreads();
    float dv = h - mu;
    red[tid] = dv * dv;
    __syncthreads();
    for (int s = 256; s > 0; s >>= 1) {
        if (tid < s) red[tid] += red[tid + s];
        __syncthreads();
    }
    float var = red[0] * (1.0f / DH);
    __syncthreads();
    float hn = dv * rsqrtf(var + 1e-5f) * ln_g[tid] + ln_b[tid];

    float p0 = hn * fc_w[tid * 2 + 0];
    float p1 = hn * fc_w[tid * 2 + 1];
    red[tid] = p0;
    __syncthreads();
    for (int s = 256; s > 0; s >>= 1) {
        if (tid < s) red[tid] += red[tid + s];
        __syncthreads();
    }
    float s0 = red[0];
    __syncthreads();
    red[tid] = p1;
    __syncthreads();
    for (int s = 256; s > 0; s >>= 1) {
        if (tid < s) red[tid] += red[tid + s];
        __syncthreads();
    }
    if (tid == 0) {
        out[0] = s0 + fc_b[0];
        out[1] = red[0] + fc_b[1];
    }
}

// ---------------- launch ---------------------------------------------------
extern "C" void kernel_launch(void* const* d_in, const int* in_sizes, int n_in,
                              void* d_out, int out_size) {
    (void)in_sizes; (void)n_in; (void)out_size;
    const float* x_s    = (const float*)d_in[0];
    const float* fc1_w  = (const float*)d_in[1];
    const float* fc1_b  = (const float*)d_in[2];
    const float* wh_w   = (const float*)d_in[3];
    const float* wh_b   = (const float*)d_in[4];
    const float* wt_w   = (const float*)d_in[5];
    const float* wt_b   = (const float*)d_in[6];
    const float* l1_w   = (const float*)d_in[7];
    const float* l1_b   = (const float*)d_in[8];
    const float* l2_w   = (const float*)d_in[9];
    const float* l2_b   = (const float*)d_in[10];
    const float* att1_w = (const float*)d_in[11];
    const float* att1_b = (const float*)d_in[12];
    const float* att2_w = (const float*)d_in[13];
    const float* att2_b = (const float*)d_in[14];
    const float* ln_g   = (const float*)d_in[15];
    const float* ln_b   = (const float*)d_in[16];
    const float* fc_w   = (const float*)d_in[17];
    const float* fc_b   = (const float*)d_in[18];
    float* out = (float*)d_out;

    static int smem_set = 0;
    if (!smem_set) {
        cudaFuncSetAttribute(k4_tc, cudaFuncAttributeMaxDynamicSharedMemorySize, SMEM4_TOTAL);
        cudaFuncSetAttribute(k1_tc, cudaFuncAttributeMaxDynamicSharedMemorySize, K1_SMEM);
        cudaFuncSetAttribute(k3_tc, cudaFuncAttributeMaxDynamicSharedMemorySize, K3_SMEM);
        cudaFuncSetAttribute(k6_tc, cudaFuncAttributeMaxDynamicSharedMemorySize, K6_SMEM);
        smem_set = 1;
    }

    dim3 gg(DH / 64, NN / 64);
    ksplit_all<<<(NSPLIT + 255) / 256, 256>>>(x_s, fc1_w, wh_w, wt_w, l1_w, l2_w);
    k1_tc<<<gg, 256, K1_SMEM>>>(fc1_b);
    k2m<<<2, 256>>>();
    k2bc_xm<<<NN / 16, 256>>>();
    k3_tc<<<gg, 256, K3_SMEM>>>(wh_b, wt_b);
    k4_tc<<<NN / 64, 512, SMEM4_TOTAL>>>();
    k45_refine_neigh<<<NN / 8, 256>>>();
    k6_tc<<<gg, 256, K6_SMEM>>>(l1_b, l2_b);
    k7_readout<<<NN / K7NODES, 256>>>(att1_w, att1_b, att2_w, att2_b);
    k8_softmax<<<1, 1024>>>();
    k9_wsum<<<dim3(4, 32), 128>>>();
    k10_final<<<1, DH>>>(ln_g, ln_b, fc_w, fc_b, out);
}